// round 13
// baseline (speedup 1.0000x reference)
#include <cuda_runtime.h>
#include <math.h>

#define NB 32
#define NA 8400
#define NM 50
#define NC 80
#define KTOP 10
#define PRED_DIM 85
#define MAXF 1536
#define BMW 263
#define INPUT_SZ 640.0f
#define PI_F 3.14159265358979323846f
#define OBJ_BLOCKS 33                          // ceil(8400/256)

// ---------------- scratch ----------------
__device__ int      g_nf[NB];
__device__ int      g_flist[NB*MAXF];
__device__ unsigned g_bitmap[NB*BMW];
__device__ float    g_cls[NB*MAXF*NC];        // cls_cost term, [b][slot][c]
__device__ float4   g_boxc[NB*MAXF];
__device__ int      g_amg[NB*NA];             // (count<<16) | sum_of_m
__device__ float    g_acc[NB*4];

// ---------------- helpers ----------------
__device__ __forceinline__ void anchor_geom(int a, float& xc, float& yc, float& cd){
    if (a < 6400){
        int y = a / 80, x = a - y*80;
        xc = (x + 0.5f)*8.f;  yc = (y + 0.5f)*8.f;  cd = 12.f;
    } else if (a < 8000){
        int i = a - 6400; int y = i / 40, x = i - y*40;
        xc = (x + 0.5f)*16.f; yc = (y + 0.5f)*16.f; cd = 24.f;
    } else {
        int i = a - 8000; int y = i / 20, x = i - y*20;
        xc = (x + 0.5f)*32.f; yc = (y + 0.5f)*32.f; cd = 48.f;
    }
}

__device__ __forceinline__ float sigmoid_f(float x){
    return 1.f / (1.f + __expf(-x));
}

__device__ __forceinline__ unsigned sortable_f(float f){
    unsigned u = __float_as_uint(f);
    return (u & 0x80000000u) ? ~u : (u | 0x80000000u);
}

__device__ __forceinline__ float bce_logits(float x, float t){
    // log1p(exp(-|x|)) ~= __logf(1+exp(-|x|)); abs err < 6e-8, additive only
    return fmaxf(x, 0.f) - x*t + __logf(1.f + __expf(-fabsf(x)));
}

// cost for (gt box, slot) — ONE definition so costK and the dup-resolution
// path produce bitwise-identical values (argmin/tie-breaks must match)
__device__ __forceinline__ float pair_cost(int a, float4 pb, float clsv,
                                           float gx, float gy, float gw, float gh,
                                           float areag){
    float xc, yc, cd; anchor_geom(a, xc, yc, cd);
    float c_l = xc - (gx - cd);
    float c_r = (gx + cd) - xc;
    float c_t = yc - (gy - cd);
    float c_b = (gy + cd) - yc;
    bool in_c = fminf(fminf(c_l,c_r), fminf(c_t,c_b)) > 0.f;
    float px=pb.x, py=pb.y, pw=pb.z, ph=pb.w;
    float tlx = fmaxf(gx-gw*0.5f, px-pw*0.5f);
    float tly = fmaxf(gy-gh*0.5f, py-ph*0.5f);
    float brx = fminf(gx+gw*0.5f, px+pw*0.5f);
    float bry = fminf(gy+gh*0.5f, py+ph*0.5f);
    float iou = 0.f;
    if (tlx<brx && tly<bry){
        float ai = (brx-tlx)*(bry-tly);
        iou = ai/(areag + pw*ph - ai);
    }
    return (clsv - 3.f*__logf(iou + 1e-8f)) + (in_c ? 0.f : 1e6f);
}

__device__ __forceinline__ float pair_iou(float4 pb, float gx, float gy,
                                          float gw, float gh, float areag){
    float px=pb.x, py=pb.y, pw=pb.z, ph=pb.w;
    float tlx = fmaxf(gx-gw*0.5f, px-pw*0.5f);
    float tly = fmaxf(gy-gh*0.5f, py-ph*0.5f);
    float brx = fminf(gx+gw*0.5f, px+pw*0.5f);
    float bry = fminf(gy+gh*0.5f, py+ph*0.5f);
    float iou = 0.f;
    if (tlx<brx && tly<bry){
        float ai = (brx-tlx)*(bry-tly);
        iou = ai/(areag + pw*ph - ai);
    }
    return iou;
}

__device__ __forceinline__ float ciou_loss(float px,float py,float pw,float ph,
                                           float gx,float gy,float gw,float gh){
    const float eps = 1e-7f;
    float px1=px-pw*0.5f, py1=py-ph*0.5f, px2=px+pw*0.5f, py2=py+ph*0.5f;
    float gx1=gx-gw*0.5f, gy1=gy-gh*0.5f, gx2=gx+gw*0.5f, gy2=gy+gh*0.5f;
    float iw = fmaxf(fminf(px2,gx2)-fmaxf(px1,gx1), 0.f);
    float ih = fmaxf(fminf(py2,gy2)-fmaxf(py1,gy1), 0.f);
    float inter = iw*ih;
    float uni = pw*ph + gw*gh - inter + eps;
    float iou = inter/uni;
    float cw = fmaxf(px2,gx2)-fminf(px1,gx1);
    float ch = fmaxf(py2,gy2)-fminf(py1,gy1);
    float c2 = cw*cw + ch*ch + eps;
    float rho2 = (gx-px)*(gx-px) + (gy-py)*(gy-py);
    float d = atanf(gw/(gh+eps)) - atanf(pw/(ph+eps));
    float v = (4.0f/(PI_F*PI_F))*d*d;
    float alpha = v/(1.f-iou+v+eps);
    return 1.f - iou + rho2/c2 + alpha*v;
}

// ---------------- kernel 0: zero state ----------------
__global__ void initK(){
    int t = blockIdx.x*blockDim.x + threadIdx.x;
    if (t < NB*NA/4) ((int4*)g_amg)[t] = make_int4(0,0,0,0);
    if (t < NB*BMW) g_bitmap[t] = 0u;
    if (t < NB*4)   g_acc[t] = 0.f;
    if (t < NB)     g_nf[t] = 0;
}

// ---------------- kernel 1: direct in-center enumeration + dedup compaction ----------------
__global__ void markK(const float* __restrict__ tgt){
    int t = blockIdx.x*blockDim.x + threadIdx.x;
    const int total = NB*NM*3*36;
    if (t >= total) return;
    int cell = t % 36; int r = t / 36;
    int level = r % 3; int bm = r / 3;
    int b = bm / NM;
    const float* tr = tgt + bm*5;
    if (tr[0] < 0.f) return;
    float gx = tr[1]*INPUT_SZ, gy = tr[2]*INPUT_SZ;
    float s, cd; int f, base;
    if (level == 0){ s = 8.f;  cd = 12.f; f = 80; base = 0;    }
    else if (level == 1){ s = 16.f; cd = 24.f; f = 40; base = 6400; }
    else { s = 32.f; cd = 48.f; f = 20; base = 8000; }
    int kx = (int)floorf(gx/s), ky = (int)floorf(gy/s);
    int ix = kx - 2 + (cell % 6);
    int iy = ky - 2 + (cell / 6);
    if (ix < 0 || ix >= f || iy < 0 || iy >= f) return;
    float xc = (ix + 0.5f)*s, yc = (iy + 0.5f)*s;
    float c_l = xc - (gx - cd);
    float c_r = (gx + cd) - xc;
    float c_t = yc - (gy - cd);
    float c_b = (gy + cd) - yc;
    if (!(fminf(fminf(c_l,c_r), fminf(c_t,c_b)) > 0.f)) return;
    int a = base + iy*f + ix;
    unsigned bit = 1u << (a & 31);
    unsigned old = atomicOr(&g_bitmap[b*BMW + (a >> 5)], bit);
    if (!(old & bit)){
        int slot = atomicAdd(&g_nf[b], 1);
        if (slot < MAXF) g_flist[b*MAXF + slot] = a;
    }
}

// ---------------- kernel 2: warp-per-slot class-cost precompute ----------------
__global__ void gatherK(const float* __restrict__ pred){
    int b = blockIdx.y;
    int slot = blockIdx.x*8 + (threadIdx.x >> 5);
    int lane = threadIdx.x & 31;
    int nf = g_nf[b]; if (nf > MAXF) nf = MAXF;
    if (slot >= nf) return;
    int a = g_flist[b*MAXF + slot];
    const float* pr = pred + ((size_t)b*NA + a)*PRED_DIM;
    float sobj = sigmoid_f(pr[4]);
    float lp0, lp1, lp2=0.f, l1m0, l1m1, l1m2=0.f;
    {
        float p = sqrtf(sigmoid_f(pr[5+lane]) * sobj);
        lp0  = fmaxf(__logf(p),       -100.f);
        l1m0 = fmaxf(__logf(1.f - p), -100.f);
    }
    {
        float p = sqrtf(sigmoid_f(pr[5+lane+32]) * sobj);
        lp1  = fmaxf(__logf(p),       -100.f);
        l1m1 = fmaxf(__logf(1.f - p), -100.f);
    }
    if (lane < 16){
        float p = sqrtf(sigmoid_f(pr[5+lane+64]) * sobj);
        lp2  = fmaxf(__logf(p),       -100.f);
        l1m2 = fmaxf(__logf(1.f - p), -100.f);
    }
    float s1m = l1m0 + l1m1 + l1m2;
    #pragma unroll
    for (int s=16; s>=1; s>>=1) s1m += __shfl_xor_sync(0xffffffffu, s1m, s);
    float* dst = g_cls + ((size_t)(b*MAXF + slot))*NC;
    dst[lane]      = -lp0 - (s1m - l1m0);
    dst[lane+32]   = -lp1 - (s1m - l1m1);
    if (lane < 16) dst[lane+64] = -lp2 - (s1m - l1m2);
    if (lane == 0) g_boxc[b*MAXF + slot] = make_float4(pr[0], pr[1], pr[2], pr[3]);
}

// ---------------- kernel 3: block-per-row cost + shrinking merge tree + scatter ----------------
__global__ void __launch_bounds__(128, 6) costK(const float* __restrict__ tgt){
    int m = blockIdx.x, b = blockIdx.y;
    int t = threadIdx.x;                 // 128 threads
    const float* tr = tgt + (b*NM+m)*5;
    float c0 = tr[0];
    if (c0 < 0.f) return;                // padded GT (block-uniform)
    int gcls = (int)fminf(fmaxf(c0, 0.f), (float)(NC-1));
    float gx = tr[1]*INPUT_SZ, gy = tr[2]*INPUT_SZ, gw = tr[3]*INPUT_SZ, gh = tr[4]*INPUT_SZ;
    float areag = gw*gh;
    int nf = g_nf[b]; if (nf > MAXF) nf = MAXF;

    unsigned long long kq[KTOP];         // ascending (cost,anchor) keys
    float iq[KTOP];                      // descending ious
    #pragma unroll
    for (int k=0;k<KTOP;k++){ kq[k]=0xFFFFFFFFFFFFFFFFull; iq[k]=0.f; }

    const int*    flst = g_flist + b*MAXF;
    const float4* boxp = g_boxc + b*MAXF;
    const float*  clsb = g_cls + (size_t)b*MAXF*NC + gcls;

    // staged loads: batch of 4 strided items -> MLP, then compute+insert
    for (int base = t; base < nf; base += 128*4){
        int av[4]; float4 pbv[4]; float clv[4]; bool ok[4];
        #pragma unroll
        for (int q=0;q<4;q++){
            int i = base + 128*q;
            ok[q] = (i < nf);
            av[q] = ok[q] ? flst[i] : 0;
        }
        #pragma unroll
        for (int q=0;q<4;q++){
            int i = base + 128*q;
            if (ok[q]){ pbv[q] = boxp[i]; clv[q] = clsb[(size_t)i*NC]; }
        }
        #pragma unroll
        for (int q=0;q<4;q++){
            if (!ok[q]) continue;
            int a = av[q];
            float4 pb = pbv[q];
            float iou = pair_iou(pb, gx, gy, gw, gh, areag);
            float cost = pair_cost(a, pb, clv[q], gx, gy, gw, gh, areag);

            unsigned long long key = ((unsigned long long)sortable_f(cost) << 32) | (unsigned)a;
            if (key < kq[KTOP-1]){
                kq[KTOP-1]=key;
                #pragma unroll
                for (int j=KTOP-1;j>0;j--){
                    if (kq[j] >= kq[j-1]) break;
                    unsigned long long tv=kq[j]; kq[j]=kq[j-1]; kq[j-1]=tv;
                }
            }
            if (iou > iq[KTOP-1]){
                iq[KTOP-1]=iou;
                #pragma unroll
                for (int j=KTOP-1;j>0;j--){
                    if (iq[j] <= iq[j-1]) break;
                    float tv=iq[j]; iq[j]=iq[j-1]; iq[j-1]=tv;
                }
            }
        }
    }

    // shrinking alternate-buffer merge tree: A(128 lists) <-> B(64 lists)
    __shared__ unsigned long long skA[128*KTOP];
    __shared__ unsigned long long skB[64*KTOP];
    __shared__ float              siA[128*KTOP];
    __shared__ float              siB[64*KTOP];
    #pragma unroll
    for (int k=0;k<KTOP;k++){ skA[t*KTOP+k]=kq[k]; siA[t*KTOP+k]=iq[k]; }

    unsigned long long* krd = skA; unsigned long long* kwr = skB;
    float* ird = siA; float* iwr = siB;
    for (int s=64; s>=1; s>>=1){
        __syncthreads();
        if (t < s){
            const unsigned long long* A = krd + t*KTOP;
            const unsigned long long* Bk = krd + (t+s)*KTOP;
            unsigned long long* D = kwr + t*KTOP;
            int i=0, j=0;
            unsigned long long av2 = A[0], bv2 = Bk[0];
            #pragma unroll
            for (int k=0;k<KTOP;k++){
                if (av2 <= bv2){ D[k]=av2; i++; av2 = (i<KTOP)? A[i] : 0xFFFFFFFFFFFFFFFFull; }
                else           { D[k]=bv2; j++; bv2 = (j<KTOP)? Bk[j]: 0xFFFFFFFFFFFFFFFFull; }
            }
            const float* Ai = ird + t*KTOP;
            const float* Bi = ird + (t+s)*KTOP;
            float* Di = iwr + t*KTOP;
            i=0; j=0;
            float af = Ai[0], bf = Bi[0];
            #pragma unroll
            for (int k=0;k<KTOP;k++){
                if (af >= bf){ Di[k]=af; i++; af = (i<KTOP)? Ai[i] : -1.f; }
                else         { Di[k]=bf; j++; bf = (j<KTOP)? Bi[j] : -1.f; }
            }
        }
        { unsigned long long* tk=krd; krd=kwr; kwr=tk; }
        { float* ti=ird; ird=iwr; iwr=ti; }
    }
    __syncthreads();

    if (t == 0){
        float sum = 0.f;
        #pragma unroll
        for (int k=0;k<KTOP;k++) sum += ird[k];
        int dk = (int)sum;                       // trunc == astype(int32)
        dk = dk < 1 ? 1 : (dk > KTOP ? KTOP : dk);
        for (int k=0;k<dk;k++){
            int a = (int)(krd[k] & 0xFFFFFFFFull);
            if (a >= 0 && a < NA)
                atomicAdd(&g_amg[b*NA + a], 0x10000 + m);
        }
    }
}

// ---------------- kernel 4: fused losses ----------------
__global__ void __launch_bounds__(256) lossposK(const float* __restrict__ pred,
                                                const float* __restrict__ tgt){
    int b = blockIdx.y;
    int t = threadIdx.x;
    int warp = t >> 5, lane = t & 31;
    if (blockIdx.x < OBJ_BLOCKS){
        int a = blockIdx.x*256 + t;
        float o = 0.f;
        if (a < NA){
            float logit = pred[((size_t)b*NA + a)*PRED_DIM + 4];
            float tf = (g_amg[b*NA + a] > 0) ? 1.f : 0.f;
            o = bce_logits(logit, tf);
        }
        #pragma unroll
        for (int d=16; d>=1; d>>=1) o += __shfl_xor_sync(0xffffffffu, o, d);
        if (lane == 0) atomicAdd(&g_acc[b*4+0], o);
        return;
    }
    // positive-slot part
    __shared__ float stg[NM*5];
    for (int i=t; i<NM*5; i+=256) stg[i] = tgt[b*NM*5+i];
    __syncthreads();
    int nf = g_nf[b]; if (nf > MAXF) nf = MAXF;
    int slot = (blockIdx.x - OBJ_BLOCKS)*8 + warp;
    if (slot >= nf) return;
    int a = g_flist[b*MAXF + slot];
    int v = g_amg[b*NA + a];
    int cnt = v >> 16;
    if (cnt == 0) return;
    int mg;
    if (cnt == 1){
        mg = v & 0xffff;
    } else {
        // recompute costs (bitwise-identical to costK), warp-parallel argmin,
        // tie-break lowest m == jnp.argmin
        float4 pb = g_boxc[b*MAXF + slot];
        unsigned long long best = 0xFFFFFFFFFFFFFFFFull;
        for (int m = lane; m < NM; m += 32){
            float c0 = stg[m*5];
            if (c0 < 0.f) continue;
            int gcls = (int)fminf(fmaxf(c0, 0.f), (float)(NC-1));
            float gx = stg[m*5+1]*INPUT_SZ, gy = stg[m*5+2]*INPUT_SZ;
            float gw = stg[m*5+3]*INPUT_SZ, gh = stg[m*5+4]*INPUT_SZ;
            float clsv = g_cls[((size_t)(b*MAXF + slot))*NC + gcls];
            float c = pair_cost(a, pb, clsv, gx, gy, gw, gh, gw*gh);
            unsigned long long key = ((unsigned long long)sortable_f(c) << 32) | (unsigned)m;
            if (key < best) best = key;
        }
        #pragma unroll
        for (int d=16; d>=1; d>>=1){
            unsigned long long o = __shfl_xor_sync(0xffffffffu, best, d);
            if (o < best) best = o;
        }
        mg = (int)(best & 0xFFFFFFFFull);
    }
    int gc = (int)fminf(fmaxf(stg[mg*5], 0.f), (float)(NC-1));
    const float* pr = pred + ((size_t)b*NA + a)*PRED_DIM;
    float cl = bce_logits(pr[5+lane],    (lane==gc)    ?1.f:0.f)
             + bce_logits(pr[5+lane+32], (lane+32==gc) ?1.f:0.f);
    if (lane < 16)
        cl += bce_logits(pr[5+lane+64], (lane+64==gc) ?1.f:0.f);
    #pragma unroll
    for (int d=16; d>=1; d>>=1) cl += __shfl_xor_sync(0xffffffffu, cl, d);
    if (lane == 0){
        float gx=stg[mg*5+1]*INPUT_SZ, gy=stg[mg*5+2]*INPUT_SZ;
        float gw=stg[mg*5+3]*INPUT_SZ, gh=stg[mg*5+4]*INPUT_SZ;
        float bx = ciou_loss(pr[0],pr[1],pr[2],pr[3], gx,gy,gw,gh);
        atomicAdd(&g_acc[b*4+1], cl);
        atomicAdd(&g_acc[b*4+2], bx);
        atomicAdd(&g_acc[b*4+3], 1.f);
    }
}

// ---------------- kernel 5: final reduction ----------------
__global__ void finalK(float* __restrict__ out){
    int t = threadIdx.x;
    float obj=0.f, cls=0.f, box=0.f, np=0.f;
    if (t < NB){
        np  = g_acc[t*4+3];
        obj = g_acc[t*4+0] / (float)NA;
        cls = (np > 0.f) ? g_acc[t*4+1]/(np*(float)NC) : 0.f;
        box = (np > 0.f) ? g_acc[t*4+2]/np : 0.f;
    }
    for (int s=16; s>=1; s>>=1){
        obj += __shfl_down_sync(0xffffffffu, obj, s);
        cls += __shfl_down_sync(0xffffffffu, cls, s);
        box += __shfl_down_sync(0xffffffffu, box, s);
        np  += __shfl_down_sync(0xffffffffu, np,  s);
    }
    if (t==0){
        float total = (5.f*box + obj + cls) / fmaxf(np, 1.f);
        out[0]=total; out[1]=box; out[2]=obj; out[3]=cls; out[4]=np;
    }
}

// ---------------- launch ----------------
extern "C" void kernel_launch(void* const* d_in, const int* in_sizes, int n_in,
                              void* d_out, int out_size){
    const float* pred = (const float*)d_in[0];   // [B, A, 85]
    const float* tgt  = (const float*)d_in[1];   // [B, M, 5]
    float* out = (float*)d_out;                  // 5 floats

    initK<<<(NB*NA/4 + 255)/256, 256>>>();
    markK<<<(NB*NM*3*36 + 255)/256, 256>>>(tgt);
    gatherK<<<dim3(MAXF/8, NB), 256>>>(pred);
    costK<<<dim3(NM, NB), 128>>>(tgt);
    lossposK<<<dim3(OBJ_BLOCKS + MAXF/8, NB), 256>>>(pred, tgt);
    finalK<<<1, 32>>>(out);
}

// round 14
// speedup vs baseline: 1.1028x; 1.1028x over previous
#include <cuda_runtime.h>
#include <math.h>

#define NB 32
#define NA 8400
#define NM 50
#define NC 80
#define KTOP 10
#define PRED_DIM 85
#define MAXF 1536
#define BMW 263
#define INPUT_SZ 640.0f
#define PI_F 3.14159265358979323846f
#define OBJ_BLOCKS 33                          // ceil(8400/256)

// ---------------- scratch ----------------
__device__ int      g_nf[NB];
__device__ int      g_flist[NB*MAXF];
__device__ unsigned g_bitmap[NB*BMW];
__device__ float    g_cls[NB*MAXF*NC];        // cls_cost term, [b][slot][c]
__device__ float4   g_boxc[NB*MAXF];
__device__ int      g_amg[NB*NA];             // (count<<16) | sum_of_m
__device__ float    g_acc[NB*4];

// ---------------- helpers ----------------
__device__ __forceinline__ void anchor_geom(int a, float& xc, float& yc, float& cd){
    if (a < 6400){
        int y = a / 80, x = a - y*80;
        xc = (x + 0.5f)*8.f;  yc = (y + 0.5f)*8.f;  cd = 12.f;
    } else if (a < 8000){
        int i = a - 6400; int y = i / 40, x = i - y*40;
        xc = (x + 0.5f)*16.f; yc = (y + 0.5f)*16.f; cd = 24.f;
    } else {
        int i = a - 8000; int y = i / 20, x = i - y*20;
        xc = (x + 0.5f)*32.f; yc = (y + 0.5f)*32.f; cd = 48.f;
    }
}

__device__ __forceinline__ float sigmoid_f(float x){
    return 1.f / (1.f + __expf(-x));
}

__device__ __forceinline__ unsigned sortable_f(float f){
    unsigned u = __float_as_uint(f);
    return (u & 0x80000000u) ? ~u : (u | 0x80000000u);
}

__device__ __forceinline__ float bce_logits(float x, float t){
    // log1p(exp(-|x|)) ~= __logf(1+exp(-|x|)); abs err < 6e-8, additive only
    return fmaxf(x, 0.f) - x*t + __logf(1.f + __expf(-fabsf(x)));
}

// cost for (gt box, slot) — ONE definition so costK and the dup-resolution
// path produce bitwise-identical values (argmin/tie-breaks must match)
__device__ __forceinline__ float pair_cost(int a, float4 pb, float clsv,
                                           float gx, float gy, float gw, float gh,
                                           float areag){
    float xc, yc, cd; anchor_geom(a, xc, yc, cd);
    float c_l = xc - (gx - cd);
    float c_r = (gx + cd) - xc;
    float c_t = yc - (gy - cd);
    float c_b = (gy + cd) - yc;
    bool in_c = fminf(fminf(c_l,c_r), fminf(c_t,c_b)) > 0.f;
    float px=pb.x, py=pb.y, pw=pb.z, ph=pb.w;
    float tlx = fmaxf(gx-gw*0.5f, px-pw*0.5f);
    float tly = fmaxf(gy-gh*0.5f, py-ph*0.5f);
    float brx = fminf(gx+gw*0.5f, px+pw*0.5f);
    float bry = fminf(gy+gh*0.5f, py+ph*0.5f);
    float iou = 0.f;
    if (tlx<brx && tly<bry){
        float ai = (brx-tlx)*(bry-tly);
        iou = ai/(areag + pw*ph - ai);
    }
    return (clsv - 3.f*__logf(iou + 1e-8f)) + (in_c ? 0.f : 1e6f);
}

__device__ __forceinline__ float pair_iou(float4 pb, float gx, float gy,
                                          float gw, float gh, float areag){
    float px=pb.x, py=pb.y, pw=pb.z, ph=pb.w;
    float tlx = fmaxf(gx-gw*0.5f, px-pw*0.5f);
    float tly = fmaxf(gy-gh*0.5f, py-ph*0.5f);
    float brx = fminf(gx+gw*0.5f, px+pw*0.5f);
    float bry = fminf(gy+gh*0.5f, py+ph*0.5f);
    float iou = 0.f;
    if (tlx<brx && tly<bry){
        float ai = (brx-tlx)*(bry-tly);
        iou = ai/(areag + pw*ph - ai);
    }
    return iou;
}

__device__ __forceinline__ float ciou_loss(float px,float py,float pw,float ph,
                                           float gx,float gy,float gw,float gh){
    const float eps = 1e-7f;
    float px1=px-pw*0.5f, py1=py-ph*0.5f, px2=px+pw*0.5f, py2=py+ph*0.5f;
    float gx1=gx-gw*0.5f, gy1=gy-gh*0.5f, gx2=gx+gw*0.5f, gy2=gy+gh*0.5f;
    float iw = fmaxf(fminf(px2,gx2)-fmaxf(px1,gx1), 0.f);
    float ih = fmaxf(fminf(py2,gy2)-fmaxf(py1,gy1), 0.f);
    float inter = iw*ih;
    float uni = pw*ph + gw*gh - inter + eps;
    float iou = inter/uni;
    float cw = fmaxf(px2,gx2)-fminf(px1,gx1);
    float ch = fmaxf(py2,gy2)-fminf(py1,gy1);
    float c2 = cw*cw + ch*ch + eps;
    float rho2 = (gx-px)*(gx-px) + (gy-py)*(gy-py);
    float d = atanf(gw/(gh+eps)) - atanf(pw/(ph+eps));
    float v = (4.0f/(PI_F*PI_F))*d*d;
    float alpha = v/(1.f-iou+v+eps);
    return 1.f - iou + rho2/c2 + alpha*v;
}

// ---------------- kernel 0: zero state ----------------
__global__ void initK(){
    int t = blockIdx.x*blockDim.x + threadIdx.x;
    if (t < NB*NA/4) ((int4*)g_amg)[t] = make_int4(0,0,0,0);
    if (t < NB*BMW) g_bitmap[t] = 0u;
    if (t < NB*4)   g_acc[t] = 0.f;
    if (t < NB)     g_nf[t] = 0;
}

// ---------------- kernel 1: direct in-center enumeration + dedup compaction ----------------
__global__ void markK(const float* __restrict__ tgt){
    int t = blockIdx.x*blockDim.x + threadIdx.x;
    const int total = NB*NM*3*36;
    if (t >= total) return;
    int cell = t % 36; int r = t / 36;
    int level = r % 3; int bm = r / 3;
    int b = bm / NM;
    const float* tr = tgt + bm*5;
    if (tr[0] < 0.f) return;
    float gx = tr[1]*INPUT_SZ, gy = tr[2]*INPUT_SZ;
    float s, cd; int f, base;
    if (level == 0){ s = 8.f;  cd = 12.f; f = 80; base = 0;    }
    else if (level == 1){ s = 16.f; cd = 24.f; f = 40; base = 6400; }
    else { s = 32.f; cd = 48.f; f = 20; base = 8000; }
    int kx = (int)floorf(gx/s), ky = (int)floorf(gy/s);
    int ix = kx - 2 + (cell % 6);
    int iy = ky - 2 + (cell / 6);
    if (ix < 0 || ix >= f || iy < 0 || iy >= f) return;
    float xc = (ix + 0.5f)*s, yc = (iy + 0.5f)*s;
    float c_l = xc - (gx - cd);
    float c_r = (gx + cd) - xc;
    float c_t = yc - (gy - cd);
    float c_b = (gy + cd) - yc;
    if (!(fminf(fminf(c_l,c_r), fminf(c_t,c_b)) > 0.f)) return;
    int a = base + iy*f + ix;
    unsigned bit = 1u << (a & 31);
    unsigned old = atomicOr(&g_bitmap[b*BMW + (a >> 5)], bit);
    if (!(old & bit)){
        int slot = atomicAdd(&g_nf[b], 1);
        if (slot < MAXF) g_flist[b*MAXF + slot] = a;
    }
}

// ---------------- kernel 2: warp-per-slot class-cost precompute ----------------
__global__ void gatherK(const float* __restrict__ pred){
    int b = blockIdx.y;
    int slot = blockIdx.x*8 + (threadIdx.x >> 5);
    int lane = threadIdx.x & 31;
    int nf = g_nf[b]; if (nf > MAXF) nf = MAXF;
    if (slot >= nf) return;
    int a = g_flist[b*MAXF + slot];
    const float* pr = pred + ((size_t)b*NA + a)*PRED_DIM;
    float sobj = sigmoid_f(pr[4]);
    float lp0, lp1, lp2=0.f, l1m0, l1m1, l1m2=0.f;
    {
        float p = sqrtf(sigmoid_f(pr[5+lane]) * sobj);
        lp0  = fmaxf(__logf(p),       -100.f);
        l1m0 = fmaxf(__logf(1.f - p), -100.f);
    }
    {
        float p = sqrtf(sigmoid_f(pr[5+lane+32]) * sobj);
        lp1  = fmaxf(__logf(p),       -100.f);
        l1m1 = fmaxf(__logf(1.f - p), -100.f);
    }
    if (lane < 16){
        float p = sqrtf(sigmoid_f(pr[5+lane+64]) * sobj);
        lp2  = fmaxf(__logf(p),       -100.f);
        l1m2 = fmaxf(__logf(1.f - p), -100.f);
    }
    float s1m = l1m0 + l1m1 + l1m2;
    #pragma unroll
    for (int s=16; s>=1; s>>=1) s1m += __shfl_xor_sync(0xffffffffu, s1m, s);
    float* dst = g_cls + ((size_t)(b*MAXF + slot))*NC;
    dst[lane]      = -lp0 - (s1m - l1m0);
    dst[lane+32]   = -lp1 - (s1m - l1m1);
    if (lane < 16) dst[lane+64] = -lp2 - (s1m - l1m2);
    if (lane == 0) g_boxc[b*MAXF + slot] = make_float4(pr[0], pr[1], pr[2], pr[3]);
}

// ---------------- kernel 3: block-per-row cost + shrinking merge tree + scatter ----------------
// R11-measured configuration: simple strided loop, launch_bounds(128,7)
__global__ void __launch_bounds__(128, 7) costK(const float* __restrict__ tgt){
    int m = blockIdx.x, b = blockIdx.y;
    int t = threadIdx.x;                 // 128 threads
    const float* tr = tgt + (b*NM+m)*5;
    float c0 = tr[0];
    if (c0 < 0.f) return;                // padded GT (block-uniform)
    int gcls = (int)fminf(fmaxf(c0, 0.f), (float)(NC-1));
    float gx = tr[1]*INPUT_SZ, gy = tr[2]*INPUT_SZ, gw = tr[3]*INPUT_SZ, gh = tr[4]*INPUT_SZ;
    float areag = gw*gh;
    int nf = g_nf[b]; if (nf > MAXF) nf = MAXF;

    unsigned long long kq[KTOP];         // ascending (cost,anchor) keys
    float iq[KTOP];                      // descending ious
    #pragma unroll
    for (int k=0;k<KTOP;k++){ kq[k]=0xFFFFFFFFFFFFFFFFull; iq[k]=0.f; }

    const int*    flst = g_flist + b*MAXF;
    const float4* boxp = g_boxc + b*MAXF;
    const float*  clsb = g_cls + (size_t)b*MAXF*NC + gcls;

    for (int i = t; i < nf; i += 128){
        int a = flst[i];
        float4 pb = boxp[i];
        float iou = pair_iou(pb, gx, gy, gw, gh, areag);
        float cost = pair_cost(a, pb, clsb[(size_t)i*NC], gx, gy, gw, gh, areag);

        unsigned long long key = ((unsigned long long)sortable_f(cost) << 32) | (unsigned)a;
        if (key < kq[KTOP-1]){
            kq[KTOP-1]=key;
            #pragma unroll
            for (int j=KTOP-1;j>0;j--){
                if (kq[j] >= kq[j-1]) break;
                unsigned long long tv=kq[j]; kq[j]=kq[j-1]; kq[j-1]=tv;
            }
        }
        if (iou > iq[KTOP-1]){
            iq[KTOP-1]=iou;
            #pragma unroll
            for (int j=KTOP-1;j>0;j--){
                if (iq[j] <= iq[j-1]) break;
                float tv=iq[j]; iq[j]=iq[j-1]; iq[j-1]=tv;
            }
        }
    }

    // shrinking alternate-buffer merge tree: A(128 lists) <-> B(64 lists)
    __shared__ unsigned long long skA[128*KTOP];
    __shared__ unsigned long long skB[64*KTOP];
    __shared__ float              siA[128*KTOP];
    __shared__ float              siB[64*KTOP];
    #pragma unroll
    for (int k=0;k<KTOP;k++){ skA[t*KTOP+k]=kq[k]; siA[t*KTOP+k]=iq[k]; }

    unsigned long long* krd = skA; unsigned long long* kwr = skB;
    float* ird = siA; float* iwr = siB;
    for (int s=64; s>=1; s>>=1){
        __syncthreads();
        if (t < s){
            const unsigned long long* A = krd + t*KTOP;
            const unsigned long long* Bk = krd + (t+s)*KTOP;
            unsigned long long* D = kwr + t*KTOP;
            int i=0, j=0;
            unsigned long long av = A[0], bv = Bk[0];
            #pragma unroll
            for (int k=0;k<KTOP;k++){
                if (av <= bv){ D[k]=av; i++; av = (i<KTOP)? A[i] : 0xFFFFFFFFFFFFFFFFull; }
                else         { D[k]=bv; j++; bv = (j<KTOP)? Bk[j]: 0xFFFFFFFFFFFFFFFFull; }
            }
            const float* Ai = ird + t*KTOP;
            const float* Bi = ird + (t+s)*KTOP;
            float* Di = iwr + t*KTOP;
            i=0; j=0;
            float af = Ai[0], bf = Bi[0];
            #pragma unroll
            for (int k=0;k<KTOP;k++){
                if (af >= bf){ Di[k]=af; i++; af = (i<KTOP)? Ai[i] : -1.f; }
                else         { Di[k]=bf; j++; bf = (j<KTOP)? Bi[j] : -1.f; }
            }
        }
        { unsigned long long* tk=krd; krd=kwr; kwr=tk; }
        { float* ti=ird; ird=iwr; iwr=ti; }
    }
    __syncthreads();

    if (t == 0){
        float sum = 0.f;
        #pragma unroll
        for (int k=0;k<KTOP;k++) sum += ird[k];
        int dk = (int)sum;                       // trunc == astype(int32)
        dk = dk < 1 ? 1 : (dk > KTOP ? KTOP : dk);
        for (int k=0;k<dk;k++){
            int a = (int)(krd[k] & 0xFFFFFFFFull);
            if (a >= 0 && a < NA)
                atomicAdd(&g_amg[b*NA + a], 0x10000 + m);
        }
    }
}

// ---------------- kernel 4: fused losses ----------------
__global__ void __launch_bounds__(256) lossposK(const float* __restrict__ pred,
                                                const float* __restrict__ tgt){
    int b = blockIdx.y;
    int t = threadIdx.x;
    int warp = t >> 5, lane = t & 31;
    if (blockIdx.x < OBJ_BLOCKS){
        int a = blockIdx.x*256 + t;
        float o = 0.f;
        if (a < NA){
            float logit = pred[((size_t)b*NA + a)*PRED_DIM + 4];
            float tf = (g_amg[b*NA + a] > 0) ? 1.f : 0.f;
            o = bce_logits(logit, tf);
        }
        #pragma unroll
        for (int d=16; d>=1; d>>=1) o += __shfl_xor_sync(0xffffffffu, o, d);
        if (lane == 0) atomicAdd(&g_acc[b*4+0], o);
        return;
    }
    // positive-slot part
    __shared__ float stg[NM*5];
    for (int i=t; i<NM*5; i+=256) stg[i] = tgt[b*NM*5+i];
    __syncthreads();
    int nf = g_nf[b]; if (nf > MAXF) nf = MAXF;
    int slot = (blockIdx.x - OBJ_BLOCKS)*8 + warp;
    if (slot >= nf) return;
    int a = g_flist[b*MAXF + slot];
    int v = g_amg[b*NA + a];
    int cnt = v >> 16;
    if (cnt == 0) return;
    int mg;
    if (cnt == 1){
        mg = v & 0xffff;
    } else {
        // recompute costs (bitwise-identical to costK), warp-parallel argmin,
        // tie-break lowest m == jnp.argmin
        float4 pb = g_boxc[b*MAXF + slot];
        unsigned long long best = 0xFFFFFFFFFFFFFFFFull;
        for (int m = lane; m < NM; m += 32){
            float c0 = stg[m*5];
            if (c0 < 0.f) continue;
            int gcls = (int)fminf(fmaxf(c0, 0.f), (float)(NC-1));
            float gx = stg[m*5+1]*INPUT_SZ, gy = stg[m*5+2]*INPUT_SZ;
            float gw = stg[m*5+3]*INPUT_SZ, gh = stg[m*5+4]*INPUT_SZ;
            float clsv = g_cls[((size_t)(b*MAXF + slot))*NC + gcls];
            float c = pair_cost(a, pb, clsv, gx, gy, gw, gh, gw*gh);
            unsigned long long key = ((unsigned long long)sortable_f(c) << 32) | (unsigned)m;
            if (key < best) best = key;
        }
        #pragma unroll
        for (int d=16; d>=1; d>>=1){
            unsigned long long o = __shfl_xor_sync(0xffffffffu, best, d);
            if (o < best) best = o;
        }
        mg = (int)(best & 0xFFFFFFFFull);
    }
    int gc = (int)fminf(fmaxf(stg[mg*5], 0.f), (float)(NC-1));
    const float* pr = pred + ((size_t)b*NA + a)*PRED_DIM;
    float cl = bce_logits(pr[5+lane],    (lane==gc)    ?1.f:0.f)
             + bce_logits(pr[5+lane+32], (lane+32==gc) ?1.f:0.f);
    if (lane < 16)
        cl += bce_logits(pr[5+lane+64], (lane+64==gc) ?1.f:0.f);
    #pragma unroll
    for (int d=16; d>=1; d>>=1) cl += __shfl_xor_sync(0xffffffffu, cl, d);
    if (lane == 0){
        float gx=stg[mg*5+1]*INPUT_SZ, gy=stg[mg*5+2]*INPUT_SZ;
        float gw=stg[mg*5+3]*INPUT_SZ, gh=stg[mg*5+4]*INPUT_SZ;
        float bx = ciou_loss(pr[0],pr[1],pr[2],pr[3], gx,gy,gw,gh);
        atomicAdd(&g_acc[b*4+1], cl);
        atomicAdd(&g_acc[b*4+2], bx);
        atomicAdd(&g_acc[b*4+3], 1.f);
    }
}

// ---------------- kernel 5: final reduction ----------------
__global__ void finalK(float* __restrict__ out){
    int t = threadIdx.x;
    float obj=0.f, cls=0.f, box=0.f, np=0.f;
    if (t < NB){
        np  = g_acc[t*4+3];
        obj = g_acc[t*4+0] / (float)NA;
        cls = (np > 0.f) ? g_acc[t*4+1]/(np*(float)NC) : 0.f;
        box = (np > 0.f) ? g_acc[t*4+2]/np : 0.f;
    }
    for (int s=16; s>=1; s>>=1){
        obj += __shfl_down_sync(0xffffffffu, obj, s);
        cls += __shfl_down_sync(0xffffffffu, cls, s);
        box += __shfl_down_sync(0xffffffffu, box, s);
        np  += __shfl_down_sync(0xffffffffu, np,  s);
    }
    if (t==0){
        float total = (5.f*box + obj + cls) / fmaxf(np, 1.f);
        out[0]=total; out[1]=box; out[2]=obj; out[3]=cls; out[4]=np;
    }
}

// ---------------- launch ----------------
extern "C" void kernel_launch(void* const* d_in, const int* in_sizes, int n_in,
                              void* d_out, int out_size){
    const float* pred = (const float*)d_in[0];   // [B, A, 85]
    const float* tgt  = (const float*)d_in[1];   // [B, M, 5]
    float* out = (float*)d_out;                  // 5 floats

    initK<<<(NB*NA/4 + 255)/256, 256>>>();
    markK<<<(NB*NM*3*36 + 255)/256, 256>>>(tgt);
    gatherK<<<dim3(MAXF/8, NB), 256>>>(pred);
    costK<<<dim3(NM, NB), 128>>>(tgt);
    lossposK<<<dim3(OBJ_BLOCKS + MAXF/8, NB), 256>>>(pred, tgt);
    finalK<<<1, 32>>>(out);
}

// round 15
// speedup vs baseline: 1.3364x; 1.2118x over previous
#include <cuda_runtime.h>
#include <math.h>

#define NB 32
#define NA 8400
#define NM 50
#define NC 80
#define KTOP 10
#define PRED_DIM 85
#define MAXF 1536
#define BMW 263
#define INPUT_SZ 640.0f
#define PI_F 3.14159265358979323846f
#define OBJ_BLOCKS 33                          // ceil(8400/256)

// ---------------- scratch ----------------
__device__ int      g_nf[NB];
__device__ int      g_flist[NB*MAXF];
__device__ int      g_cidx[NB*NA];            // anchor -> slot (written only for marked anchors)
__device__ unsigned g_bitmap[NB*BMW];
__device__ float    g_cls[NB*MAXF*NC];        // cls_cost term, [b][slot][c]
__device__ float4   g_boxc[NB*MAXF];
__device__ int      g_amg[NB*NA];             // (count<<16) | sum_of_m
__device__ float    g_acc[NB*4];

// ---------------- helpers ----------------
__device__ __forceinline__ void anchor_geom(int a, float& xc, float& yc, float& cd){
    if (a < 6400){
        int y = a / 80, x = a - y*80;
        xc = (x + 0.5f)*8.f;  yc = (y + 0.5f)*8.f;  cd = 12.f;
    } else if (a < 8000){
        int i = a - 6400; int y = i / 40, x = i - y*40;
        xc = (x + 0.5f)*16.f; yc = (y + 0.5f)*16.f; cd = 24.f;
    } else {
        int i = a - 8000; int y = i / 20, x = i - y*20;
        xc = (x + 0.5f)*32.f; yc = (y + 0.5f)*32.f; cd = 48.f;
    }
}

__device__ __forceinline__ float sigmoid_f(float x){
    return 1.f / (1.f + __expf(-x));
}

__device__ __forceinline__ unsigned sortable_f(float f){
    unsigned u = __float_as_uint(f);
    return (u & 0x80000000u) ? ~u : (u | 0x80000000u);
}

__device__ __forceinline__ float bce_logits(float x, float t){
    return fmaxf(x, 0.f) - x*t + __logf(1.f + __expf(-fabsf(x)));
}

// cost for (gt box, slot) — ONE definition so costK and the dup-resolution
// path produce bitwise-identical values (argmin/tie-breaks must match)
__device__ __forceinline__ float pair_cost(int a, float4 pb, float clsv,
                                           float gx, float gy, float gw, float gh,
                                           float areag){
    float xc, yc, cd; anchor_geom(a, xc, yc, cd);
    float c_l = xc - (gx - cd);
    float c_r = (gx + cd) - xc;
    float c_t = yc - (gy - cd);
    float c_b = (gy + cd) - yc;
    bool in_c = fminf(fminf(c_l,c_r), fminf(c_t,c_b)) > 0.f;
    float px=pb.x, py=pb.y, pw=pb.z, ph=pb.w;
    float tlx = fmaxf(gx-gw*0.5f, px-pw*0.5f);
    float tly = fmaxf(gy-gh*0.5f, py-ph*0.5f);
    float brx = fminf(gx+gw*0.5f, px+pw*0.5f);
    float bry = fminf(gy+gh*0.5f, py+ph*0.5f);
    float iou = 0.f;
    if (tlx<brx && tly<bry){
        float ai = (brx-tlx)*(bry-tly);
        iou = ai/(areag + pw*ph - ai);
    }
    return (clsv - 3.f*__logf(iou + 1e-8f)) + (in_c ? 0.f : 1e6f);
}

__device__ __forceinline__ float pair_iou(float4 pb, float gx, float gy,
                                          float gw, float gh, float areag){
    float px=pb.x, py=pb.y, pw=pb.z, ph=pb.w;
    float tlx = fmaxf(gx-gw*0.5f, px-pw*0.5f);
    float tly = fmaxf(gy-gh*0.5f, py-ph*0.5f);
    float brx = fminf(gx+gw*0.5f, px+pw*0.5f);
    float bry = fminf(gy+gh*0.5f, py+ph*0.5f);
    float iou = 0.f;
    if (tlx<brx && tly<bry){
        float ai = (brx-tlx)*(bry-tly);
        iou = ai/(areag + pw*ph - ai);
    }
    return iou;
}

__device__ __forceinline__ float ciou_loss(float px,float py,float pw,float ph,
                                           float gx,float gy,float gw,float gh){
    const float eps = 1e-7f;
    float px1=px-pw*0.5f, py1=py-ph*0.5f, px2=px+pw*0.5f, py2=py+ph*0.5f;
    float gx1=gx-gw*0.5f, gy1=gy-gh*0.5f, gx2=gx+gw*0.5f, gy2=gy+gh*0.5f;
    float iw = fmaxf(fminf(px2,gx2)-fmaxf(px1,gx1), 0.f);
    float ih = fmaxf(fminf(py2,gy2)-fmaxf(py1,gy1), 0.f);
    float inter = iw*ih;
    float uni = pw*ph + gw*gh - inter + eps;
    float iou = inter/uni;
    float cw = fmaxf(px2,gx2)-fminf(px1,gx1);
    float ch = fmaxf(py2,gy2)-fminf(py1,gy1);
    float c2 = cw*cw + ch*ch + eps;
    float rho2 = (gx-px)*(gx-px) + (gy-py)*(gy-py);
    float d = atanf(gw/(gh+eps)) - atanf(pw/(ph+eps));
    float v = (4.0f/(PI_F*PI_F))*d*d;
    float alpha = v/(1.f-iou+v+eps);
    return 1.f - iou + rho2/c2 + alpha*v;
}

// ---------------- kernel 0: zero state ----------------
__global__ void initK(){
    int t = blockIdx.x*blockDim.x + threadIdx.x;
    if (t < NB*NA/4) ((int4*)g_amg)[t] = make_int4(0,0,0,0);
    if (t < NB*BMW) g_bitmap[t] = 0u;
    if (t < NB*4)   g_acc[t] = 0.f;
    if (t < NB)     g_nf[t] = 0;
}

// ---------------- kernel 1: direct in-center enumeration + dedup compaction ----------------
__global__ void markK(const float* __restrict__ tgt){
    int t = blockIdx.x*blockDim.x + threadIdx.x;
    const int total = NB*NM*3*36;
    if (t >= total) return;
    int cell = t % 36; int r = t / 36;
    int level = r % 3; int bm = r / 3;
    int b = bm / NM;
    const float* tr = tgt + bm*5;
    if (tr[0] < 0.f) return;
    float gx = tr[1]*INPUT_SZ, gy = tr[2]*INPUT_SZ;
    float s, cd; int f, base;
    if (level == 0){ s = 8.f;  cd = 12.f; f = 80; base = 0;    }
    else if (level == 1){ s = 16.f; cd = 24.f; f = 40; base = 6400; }
    else { s = 32.f; cd = 48.f; f = 20; base = 8000; }
    int kx = (int)floorf(gx/s), ky = (int)floorf(gy/s);
    int ix = kx - 2 + (cell % 6);
    int iy = ky - 2 + (cell / 6);
    if (ix < 0 || ix >= f || iy < 0 || iy >= f) return;
    float xc = (ix + 0.5f)*s, yc = (iy + 0.5f)*s;
    float c_l = xc - (gx - cd);
    float c_r = (gx + cd) - xc;
    float c_t = yc - (gy - cd);
    float c_b = (gy + cd) - yc;
    if (!(fminf(fminf(c_l,c_r), fminf(c_t,c_b)) > 0.f)) return;
    int a = base + iy*f + ix;
    unsigned bit = 1u << (a & 31);
    unsigned old = atomicOr(&g_bitmap[b*BMW + (a >> 5)], bit);
    if (!(old & bit)){
        int slot = atomicAdd(&g_nf[b], 1);
        if (slot < MAXF){
            g_flist[b*MAXF + slot] = a;
            g_cidx[b*NA + a] = slot;
        }
    }
}

// ---------------- kernel 2: warp-per-slot class-cost precompute ----------------
__global__ void gatherK(const float* __restrict__ pred){
    int b = blockIdx.y;
    int slot = blockIdx.x*8 + (threadIdx.x >> 5);
    int lane = threadIdx.x & 31;
    int nf = g_nf[b]; if (nf > MAXF) nf = MAXF;
    if (slot >= nf) return;
    int a = g_flist[b*MAXF + slot];
    const float* pr = pred + ((size_t)b*NA + a)*PRED_DIM;
    float sobj = sigmoid_f(pr[4]);
    float lp0, lp1, lp2=0.f, l1m0, l1m1, l1m2=0.f;
    {
        float p = sqrtf(sigmoid_f(pr[5+lane]) * sobj);
        lp0  = fmaxf(__logf(p),       -100.f);
        l1m0 = fmaxf(__logf(1.f - p), -100.f);
    }
    {
        float p = sqrtf(sigmoid_f(pr[5+lane+32]) * sobj);
        lp1  = fmaxf(__logf(p),       -100.f);
        l1m1 = fmaxf(__logf(1.f - p), -100.f);
    }
    if (lane < 16){
        float p = sqrtf(sigmoid_f(pr[5+lane+64]) * sobj);
        lp2  = fmaxf(__logf(p),       -100.f);
        l1m2 = fmaxf(__logf(1.f - p), -100.f);
    }
    float s1m = l1m0 + l1m1 + l1m2;
    #pragma unroll
    for (int s=16; s>=1; s>>=1) s1m += __shfl_xor_sync(0xffffffffu, s1m, s);
    float* dst = g_cls + ((size_t)(b*MAXF + slot))*NC;
    dst[lane]      = -lp0 - (s1m - l1m0);
    dst[lane+32]   = -lp1 - (s1m - l1m1);
    if (lane < 16) dst[lane+64] = -lp2 - (s1m - l1m2);
    if (lane == 0) g_boxc[b*MAXF + slot] = make_float4(pr[0], pr[1], pr[2], pr[3]);
}

// ---------------- kernel 3: block-per-row; iou over all filtered, cost over in-center window ----------------
__global__ void __launch_bounds__(128, 7) costK(const float* __restrict__ tgt){
    int m = blockIdx.x, b = blockIdx.y;
    int t = threadIdx.x;                 // 128 threads
    const float* tr = tgt + (b*NM+m)*5;
    float c0 = tr[0];
    if (c0 < 0.f) return;                // padded GT (block-uniform)
    int gcls = (int)fminf(fmaxf(c0, 0.f), (float)(NC-1));
    float gx = tr[1]*INPUT_SZ, gy = tr[2]*INPUT_SZ, gw = tr[3]*INPUT_SZ, gh = tr[4]*INPUT_SZ;
    float areag = gw*gh;
    int nf = g_nf[b]; if (nf > MAXF) nf = MAXF;

    unsigned long long kq[KTOP];         // ascending (cost,anchor) keys
    float iq[KTOP];                      // descending ious
    #pragma unroll
    for (int k=0;k<KTOP;k++){ kq[k]=0xFFFFFFFFFFFFFFFFull; iq[k]=0.f; }

    const float4* boxp = g_boxc + b*MAXF;
    const float*  clsb = g_cls + (size_t)b*MAXF*NC + gcls;

    // (1) iou top-10 over ALL filtered anchors (needed for dyn_k) — cheap loop
    for (int i = t; i < nf; i += 128){
        float iou = pair_iou(boxp[i], gx, gy, gw, gh, areag);
        if (iou > iq[KTOP-1]){
            iq[KTOP-1]=iou;
            #pragma unroll
            for (int j=KTOP-1;j>0;j--){
                if (iq[j] <= iq[j-1]) break;
                float tv=iq[j]; iq[j]=iq[j-1]; iq[j-1]=tv;
            }
        }
    }

    // (2) cost top-10 over this GT's in-center window only.
    // Any in-center cost < 8.2e3; any non-in-center cost >= ~1e6; and every
    // valid GT has >=12 in-center anchors => global top-10 lies in this set.
    if (t < 75){
        int level = t / 25, cell = t - level*25;
        float s, cd; int f, base;
        if (level == 0){ s = 8.f;  cd = 12.f; f = 80; base = 0;    }
        else if (level == 1){ s = 16.f; cd = 24.f; f = 40; base = 6400; }
        else { s = 32.f; cd = 48.f; f = 20; base = 8000; }
        int kx = (int)floorf(gx/s), ky = (int)floorf(gy/s);
        int ix = kx - 2 + (cell % 5);
        int iy = ky - 2 + (cell / 5);
        if (ix >= 0 && ix < f && iy >= 0 && iy < f){
            float xc = (ix + 0.5f)*s, yc = (iy + 0.5f)*s;
            float c_l = xc - (gx - cd);
            float c_r = (gx + cd) - xc;
            float c_t = yc - (gy - cd);
            float c_b = (gy + cd) - yc;
            if (fminf(fminf(c_l,c_r), fminf(c_t,c_b)) > 0.f){
                int a = base + iy*f + ix;
                int slot = g_cidx[b*NA + a];     // marked => valid slot
                if (slot >= 0 && slot < MAXF){
                    float cost = pair_cost(a, boxp[slot], clsb[(size_t)slot*NC],
                                           gx, gy, gw, gh, areag);
                    unsigned long long key =
                        ((unsigned long long)sortable_f(cost) << 32) | (unsigned)a;
                    kq[KTOP-1] = key;            // list was empty: place & done
                    #pragma unroll
                    for (int j=KTOP-1;j>0;j--){
                        if (kq[j] >= kq[j-1]) break;
                        unsigned long long tv=kq[j]; kq[j]=kq[j-1]; kq[j-1]=tv;
                    }
                }
            }
        }
    }

    // shrinking alternate-buffer merge tree: A(128 lists) <-> B(64 lists)
    __shared__ unsigned long long skA[128*KTOP];
    __shared__ unsigned long long skB[64*KTOP];
    __shared__ float              siA[128*KTOP];
    __shared__ float              siB[64*KTOP];
    #pragma unroll
    for (int k=0;k<KTOP;k++){ skA[t*KTOP+k]=kq[k]; siA[t*KTOP+k]=iq[k]; }

    unsigned long long* krd = skA; unsigned long long* kwr = skB;
    float* ird = siA; float* iwr = siB;
    for (int s=64; s>=1; s>>=1){
        __syncthreads();
        if (t < s){
            const unsigned long long* A = krd + t*KTOP;
            const unsigned long long* Bk = krd + (t+s)*KTOP;
            unsigned long long* D = kwr + t*KTOP;
            int i=0, j=0;
            unsigned long long av = A[0], bv = Bk[0];
            #pragma unroll
            for (int k=0;k<KTOP;k++){
                if (av <= bv){ D[k]=av; i++; av = (i<KTOP)? A[i] : 0xFFFFFFFFFFFFFFFFull; }
                else         { D[k]=bv; j++; bv = (j<KTOP)? Bk[j]: 0xFFFFFFFFFFFFFFFFull; }
            }
            const float* Ai = ird + t*KTOP;
            const float* Bi = ird + (t+s)*KTOP;
            float* Di = iwr + t*KTOP;
            i=0; j=0;
            float af = Ai[0], bf = Bi[0];
            #pragma unroll
            for (int k=0;k<KTOP;k++){
                if (af >= bf){ Di[k]=af; i++; af = (i<KTOP)? Ai[i] : -1.f; }
                else         { Di[k]=bf; j++; bf = (j<KTOP)? Bi[j] : -1.f; }
            }
        }
        { unsigned long long* tk=krd; krd=kwr; kwr=tk; }
        { float* ti=ird; ird=iwr; iwr=ti; }
    }
    __syncthreads();

    if (t == 0){
        float sum = 0.f;
        #pragma unroll
        for (int k=0;k<KTOP;k++) sum += ird[k];
        int dk = (int)sum;                       // trunc == astype(int32)
        dk = dk < 1 ? 1 : (dk > KTOP ? KTOP : dk);
        for (int k=0;k<dk;k++){
            int a = (int)(krd[k] & 0xFFFFFFFFull);
            if (a >= 0 && a < NA)
                atomicAdd(&g_amg[b*NA + a], 0x10000 + m);
        }
    }
}

// ---------------- kernel 4: fused losses ----------------
__global__ void __launch_bounds__(256) lossposK(const float* __restrict__ pred,
                                                const float* __restrict__ tgt){
    int b = blockIdx.y;
    int t = threadIdx.x;
    int warp = t >> 5, lane = t & 31;
    if (blockIdx.x < OBJ_BLOCKS){
        int a = blockIdx.x*256 + t;
        float o = 0.f;
        if (a < NA){
            float logit = pred[((size_t)b*NA + a)*PRED_DIM + 4];
            float tf = (g_amg[b*NA + a] > 0) ? 1.f : 0.f;
            o = bce_logits(logit, tf);
        }
        #pragma unroll
        for (int d=16; d>=1; d>>=1) o += __shfl_xor_sync(0xffffffffu, o, d);
        if (lane == 0) atomicAdd(&g_acc[b*4+0], o);
        return;
    }
    // positive-slot part
    __shared__ float stg[NM*5];
    for (int i=t; i<NM*5; i+=256) stg[i] = tgt[b*NM*5+i];
    __syncthreads();
    int nf = g_nf[b]; if (nf > MAXF) nf = MAXF;
    int slot = (blockIdx.x - OBJ_BLOCKS)*8 + warp;
    if (slot >= nf) return;
    int a = g_flist[b*MAXF + slot];
    int v = g_amg[b*NA + a];
    int cnt = v >> 16;
    if (cnt == 0) return;
    int mg;
    if (cnt == 1){
        mg = v & 0xffff;
    } else {
        // recompute costs (bitwise-identical to costK), warp-parallel argmin,
        // tie-break lowest m == jnp.argmin
        float4 pb = g_boxc[b*MAXF + slot];
        unsigned long long best = 0xFFFFFFFFFFFFFFFFull;
        for (int m = lane; m < NM; m += 32){
            float c0 = stg[m*5];
            if (c0 < 0.f) continue;
            int gcls = (int)fminf(fmaxf(c0, 0.f), (float)(NC-1));
            float gx = stg[m*5+1]*INPUT_SZ, gy = stg[m*5+2]*INPUT_SZ;
            float gw = stg[m*5+3]*INPUT_SZ, gh = stg[m*5+4]*INPUT_SZ;
            float clsv = g_cls[((size_t)(b*MAXF + slot))*NC + gcls];
            float c = pair_cost(a, pb, clsv, gx, gy, gw, gh, gw*gh);
            unsigned long long key = ((unsigned long long)sortable_f(c) << 32) | (unsigned)m;
            if (key < best) best = key;
        }
        #pragma unroll
        for (int d=16; d>=1; d>>=1){
            unsigned long long o = __shfl_xor_sync(0xffffffffu, best, d);
            if (o < best) best = o;
        }
        mg = (int)(best & 0xFFFFFFFFull);
    }
    int gc = (int)fminf(fmaxf(stg[mg*5], 0.f), (float)(NC-1));
    const float* pr = pred + ((size_t)b*NA + a)*PRED_DIM;
    float cl = bce_logits(pr[5+lane],    (lane==gc)    ?1.f:0.f)
             + bce_logits(pr[5+lane+32], (lane+32==gc) ?1.f:0.f);
    if (lane < 16)
        cl += bce_logits(pr[5+lane+64], (lane+64==gc) ?1.f:0.f);
    #pragma unroll
    for (int d=16; d>=1; d>>=1) cl += __shfl_xor_sync(0xffffffffu, cl, d);
    if (lane == 0){
        float gx=stg[mg*5+1]*INPUT_SZ, gy=stg[mg*5+2]*INPUT_SZ;
        float gw=stg[mg*5+3]*INPUT_SZ, gh=stg[mg*5+4]*INPUT_SZ;
        float bx = ciou_loss(pr[0],pr[1],pr[2],pr[3], gx,gy,gw,gh);
        atomicAdd(&g_acc[b*4+1], cl);
        atomicAdd(&g_acc[b*4+2], bx);
        atomicAdd(&g_acc[b*4+3], 1.f);
    }
}

// ---------------- kernel 5: final reduction ----------------
__global__ void finalK(float* __restrict__ out){
    int t = threadIdx.x;
    float obj=0.f, cls=0.f, box=0.f, np=0.f;
    if (t < NB){
        np  = g_acc[t*4+3];
        obj = g_acc[t*4+0] / (float)NA;
        cls = (np > 0.f) ? g_acc[t*4+1]/(np*(float)NC) : 0.f;
        box = (np > 0.f) ? g_acc[t*4+2]/np : 0.f;
    }
    for (int s=16; s>=1; s>>=1){
        obj += __shfl_down_sync(0xffffffffu, obj, s);
        cls += __shfl_down_sync(0xffffffffu, cls, s);
        box += __shfl_down_sync(0xffffffffu, box, s);
        np  += __shfl_down_sync(0xffffffffu, np,  s);
    }
    if (t==0){
        float total = (5.f*box + obj + cls) / fmaxf(np, 1.f);
        out[0]=total; out[1]=box; out[2]=obj; out[3]=cls; out[4]=np;
    }
}

// ---------------- launch ----------------
extern "C" void kernel_launch(void* const* d_in, const int* in_sizes, int n_in,
                              void* d_out, int out_size){
    const float* pred = (const float*)d_in[0];   // [B, A, 85]
    const float* tgt  = (const float*)d_in[1];   // [B, M, 5]
    float* out = (float*)d_out;                  // 5 floats

    initK<<<(NB*NA/4 + 255)/256, 256>>>();
    markK<<<(NB*NM*3*36 + 255)/256, 256>>>(tgt);
    gatherK<<<dim3(MAXF/8, NB), 256>>>(pred);
    costK<<<dim3(NM, NB), 128>>>(tgt);
    lossposK<<<dim3(OBJ_BLOCKS + MAXF/8, NB), 256>>>(pred, tgt);
    finalK<<<1, 32>>>(out);
}